// round 12
// baseline (speedup 1.0000x reference)
#include <cuda_runtime.h>
#include <cuda_bf16.h>
#include <cstdint>

#define NM     512
#define BATCH  32
#define DIMK   64
#define BIGF   1e30f
#define SENTU  0x7fc00000u

// Packed D (pre-scaled by log2 e): g_Dq[b][W][u][k] as float2.
// W = warp row-group (rows 64W+2k, 64W+2k+1), u = local step, col j = u-2k.
#define UROWS 592
__device__ __align__(16) float g_Dq[(size_t)BATCH * 8 * UROWS * 64];

// Boundary rings: producer (warp w) publishes v1(u-1) at slot u.
// value(col c) lives at slot c+63. Slots 0..575 written; rest preinit BIG.
#define RING 656

__device__ __forceinline__ float ex2f(float x) {
    float r; asm("ex2.approx.f32 %0, %1;" : "=f"(r) : "f"(x)); return r;
}
__device__ __forceinline__ float lg2f(float x) {
    float r; asm("lg2.approx.f32 %0, %1;" : "=f"(r) : "f"(x)); return r;
}
// smem spin (raw backward branch, no BSSY): wait until *p != sentinel.
__device__ __forceinline__ float spinv(const float* p) {
    unsigned a = (unsigned)__cvta_generic_to_shared(p);
    unsigned v;
    asm volatile(
        "{\n\t.reg .pred sp;\n"
        "SPINS%=:\n\t"
        "ld.volatile.shared.b32 %0, [%1];\n\t"
        "setp.eq.u32 sp, %0, 0x7fc00000;\n\t"
        "@sp bra SPINS%=;\n\t}"
        : "=r"(v) : "r"(a) : "memory");
    return __uint_as_float(v);
}
__device__ __forceinline__ void sts_vol(float* p, float v) {
    unsigned a = (unsigned)__cvta_generic_to_shared(p);
    asm volatile("st.volatile.shared.b32 [%0], %1;" :: "r"(a), "f"(v) : "memory");
}

// ---------------------------------------------------------------------------
// Kernel 1: pairwise sqdist * log2(e) packed into g_Dq.
// 64x64 tiles (i-tile == warp row-group W), 256 threads, 4x4 microtiles.
// ---------------------------------------------------------------------------
__global__ void __launch_bounds__(256) pairdist_kernel(
    const float* __restrict__ X, const float* __restrict__ Y)
{
    __shared__ __align__(16) float Xs[64 * 68];
    __shared__ __align__(16) float Ys[64 * 68];
    __shared__ __align__(16) float x2s[64];
    __shared__ __align__(16) float y2s[64];
    __shared__ __align__(16) float stage[64 * 66];   // stage[jl*66 + il]

    const int b  = blockIdx.z;
    const int i0 = blockIdx.x * 64;                  // W = blockIdx.x
    const int j0 = blockIdx.y * 64;
    const int tid = threadIdx.x;

    const float* Xb = X + ((size_t)b * NM + i0) * DIMK;
    const float* Yb = Y + ((size_t)b * NM + j0) * DIMK;

    for (int t = tid; t < 64 * 64; t += 256) {
        int r = t >> 6, k = t & 63;
        Xs[k * 68 + r] = Xb[r * DIMK + k];
        Ys[k * 68 + r] = Yb[r * DIMK + k];
    }
    __syncthreads();

    if (tid < 128) {
        int r = tid & 63;
        const float* S = (tid < 64) ? Xs : Ys;
        float acc = 0.f;
        #pragma unroll 8
        for (int k = 0; k < 64; ++k) { float v = S[k * 68 + r]; acc += v * v; }
        if (tid < 64) x2s[r] = acc; else y2s[r] = acc;
    }
    __syncthreads();

    const int tx = tid & 15, ty = tid >> 4;
    float acc[4][4];
    #pragma unroll
    for (int a = 0; a < 4; ++a)
        #pragma unroll
        for (int c = 0; c < 4; ++c) acc[a][c] = 0.f;

    #pragma unroll 8
    for (int k = 0; k < 64; ++k) {
        float4 xv = *(const float4*)&Xs[k * 68 + 4 * tx];
        float4 yv = *(const float4*)&Ys[k * 68 + 4 * ty];
        float xr[4] = {xv.x, xv.y, xv.z, xv.w};
        float yr[4] = {yv.x, yv.y, yv.z, yv.w};
        #pragma unroll
        for (int jj = 0; jj < 4; ++jj)
            #pragma unroll
            for (int ii = 0; ii < 4; ++ii)
                acc[jj][ii] += yr[jj] * xr[ii];
    }

    const float L2E = 1.4426950408889634f;
    float4 x2v = *(const float4*)&x2s[4 * tx];
    float xr2[4] = {x2v.x, x2v.y, x2v.z, x2v.w};
    #pragma unroll
    for (int jj = 0; jj < 4; ++jj) {
        float y2 = y2s[4 * ty + jj];
        #pragma unroll
        for (int ii = 0; ii < 4; ++ii)
            stage[(4 * ty + jj) * 66 + 4 * tx + ii] =
                (xr2[ii] + y2 - 2.f * acc[jj][ii]) * L2E;
    }
    __syncthreads();

    // Packed writeout: local step row c = jl + 2k; lane = k.
    const int wk   = tid >> 5;
    const int lane = tid & 31;
    float2* gout = (float2*)g_Dq + ((size_t)(b * 8 + blockIdx.x) * UROWS + j0) * 32;
    for (int c = wk; c < 126; c += 8) {
        int jl = c - 2 * lane;
        if ((unsigned)jl < 64u) {
            float2 p = *(const float2*)&stage[jl * 66 + 2 * lane];
            gout[(size_t)c * 32 + lane] = p;
        }
    }
}

// ---------------------------------------------------------------------------
// Kernel 2: soft-DTW, skew-2 wavefront, software-pipelined, TWO batches per
// CTA. 16 CTAs x 512 threads. Warps 0-7: batch 2*bx (rows 64w..); warps 8-15:
// batch 2*bx+1. The two wavefronts are independent -> 4 warps/SMSP from two
// uncorrelated pipelines hide each other's MUFU/shfl latency.
// ---------------------------------------------------------------------------
__global__ void __launch_bounds__(512, 1) sdtw_kernel(float* __restrict__ out)
{
    __shared__ __align__(16) float rings[2][9][RING];

    const int bx   = blockIdx.x;
    const int tid  = threadIdx.x;
    const int w    = tid >> 5;          // 0..15
    const int wl   = w & 7;             // warp within batch-half
    const int hb   = w >> 3;            // which batch half
    const int b    = 2 * bx + hb;
    const int lane = tid & 31;
    const bool is0  = (lane == 0);
    const bool is31 = (lane == 31);

    for (int t = tid; t < 2 * 9 * RING; t += 512) {
        int r = (t / RING) % 9, s = t % RING;
        bool sent = (r >= 1) && (s < 576);
        rings[0][0][t] = sent ? __uint_as_float(SENTU) : BIGF;   // flat fill
    }
    __syncthreads();

    // D prefetch ring (float2 per lane per step).
    const float2* dp0 = (const float2*)g_Dq + (size_t)(b * 8 + wl) * UROWS * 32 + lane;
    float2 dring[8];
    #pragma unroll
    for (int p = 0; p < 8; ++p) dring[p] = dp0[p * 32];
    const float2* dp = dp0 + 8 * 32;

    const float* rring = rings[hb][wl];       // consumer: value(col c) at slot c+63
    float*       wring = rings[hb][wl + 1];   // producer: iter u writes slot u

    // Prefill: P(-1) at slot 62, P(0) at slot 63.
    float pm1 = spinv(rring + 62);
    float p0  = spinv(rring + 63);
    if (lane != 0) { pm1 = BIGF; p0 = BIGF; }
    if (wl == 0 && lane == 0) pm1 = 0.0f;     // each batch's origin: R[-1][-1]=0
    float lo0  = fminf(pm1, p0), hi0 = fmaxf(pm1, p0);
    float pNow = p0;

    // First chunk: slots 64..71 = P(1..8).
    float bnd[8];
    {
        (void)spinv(rring + 71);
        float4 c0 = *(const float4*)(rring + 64);
        float4 c1 = *(const float4*)(rring + 68);
        bnd[0]=c0.x; bnd[1]=c0.y; bnd[2]=c0.z; bnd[3]=c0.w;
        bnd[4]=c1.x; bnd[5]=c1.y; bnd[6]=c1.z; bnd[7]=c1.w;
    }

    float v0p  = BIGF;                 // v0(u-1)
    float d2yp = 0.f;                  // d(u-1).y
    float lo1p = BIGF, hi1p = BIGF;    // min/max(v0(u-2), v1(u-2))
    float res  = 0.f;

    for (int B = 0; B < 576; B += 8) {
        #pragma unroll
        for (int x = 0; x < 8; ++x) {
            float2 d2 = dring[x];
            dring[x] = dp[x * 32];                 // prefetch step u+8

            // cell0(u): softmin(P(j-1), P(j), v0(u-1))
            float m0 = fminf(lo0, v0p);
            float x0 = fmaxf(lo0, v0p);
            float v0 = (d2.x + m0) - lg2f(ex2f(m0 - x0) + ex2f(m0 - hi0) + 1.0f);

            // cell1(u-1): softmin(v0(u-2), v1(u-2), v0(u-1)) -- parallel with v0(u)
            float m1  = fminf(lo1p, v0p);
            float x1  = fmaxf(lo1p, v0p);
            float v1m = (d2yp + m1) - lg2f(ex2f(m1 - x1) + ex2f(m1 - hi1p) + 1.0f);

            if (x == 6) { if (B == 568) res = v1m; }   // iter 574 -> v1(573) = R[511][511]

            if (is31) sts_vol(wring + (B + x), v1m);   // publish slot u

            float sh = __shfl_up_sync(0xffffffffu, v1m, 1);
            float newv = is0 ? bnd[x] : sh;            // P(u+1)

            if (x == 7) {                              // next chunk: slots B+72..79
                (void)spinv(rring + B + 79);
                float4 c0 = *(const float4*)(rring + B + 72);
                float4 c1 = *(const float4*)(rring + B + 76);
                bnd[0]=c0.x; bnd[1]=c0.y; bnd[2]=c0.z; bnd[3]=c0.w;
                bnd[4]=c1.x; bnd[5]=c1.y; bnd[6]=c1.z; bnd[7]=c1.w;
            }

            // rolls (off the v0 chain)
            lo1p = fminf(v0p, v1m);
            hi1p = fmaxf(v0p, v1m);
            lo0  = fminf(pNow, newv);
            hi0  = fmaxf(pNow, newv);
            pNow = newv;
            v0p  = v0;
            d2yp = d2.y;
        }
        dp += 8 * 32;
    }

    if ((tid & 255) == 255)                            // tid 255 -> b=2bx; 511 -> 2bx+1
        out[b] = res * 0.69314718055994531f;           // log2 -> natural domain
}

extern "C" void kernel_launch(void* const* d_in, const int* in_sizes, int n_in,
                              void* d_out, int out_size)
{
    (void)in_sizes; (void)n_in; (void)out_size;
    const float* X = (const float*)d_in[0];
    const float* Y = (const float*)d_in[1];
    float* out = (float*)d_out;

    dim3 g1(NM / 64, NM / 64, BATCH);
    pairdist_kernel<<<g1, 256>>>(X, Y);
    sdtw_kernel<<<BATCH / 2, 512>>>(out);
}

// round 13
// speedup vs baseline: 1.0167x; 1.0167x over previous
#include <cuda_runtime.h>
#include <cuda_bf16.h>
#include <cuda_fp16.h>
#include <cstdint>

#define NM     512
#define BATCH  32
#define DIMK   64
#define BIGF   1e30f
#define SENTU  0x7fc00000u

// Packed D (pre-scaled by log2 e): g_Dq[b][W][u][k] as float2.
// W = warp row-group (rows 64W+2k, 64W+2k+1), u = local step, col j = u-2k.
#define UROWS 592
__device__ __align__(16) float g_Dq[(size_t)BATCH * 8 * UROWS * 64];

// Boundary rings: producer (warp w) publishes v1(u-1) at slot u.
// value(col c) lives at slot c+63. Slots 0..575 written; rest preinit BIG.
#define RING 656

__device__ __forceinline__ float ex2f(float x) {
    float r; asm("ex2.approx.f32 %0, %1;" : "=f"(r) : "f"(x)); return r;
}
__device__ __forceinline__ float lg2f(float x) {
    float r; asm("lg2.approx.f32 %0, %1;" : "=f"(r) : "f"(x)); return r;
}
// Fused dual exp2 on the MUFU f16x2 path: returns 2^a + 2^b (a,b <= 0).
__device__ __forceinline__ float ex2_pair(float a, float b) {
    __half2 h = h2exp2(__floats2half2_rn(a, b));
    return __low2float(h) + __high2float(h);
}
// smem spin (raw backward branch, no BSSY): wait until *p != sentinel.
__device__ __forceinline__ float spinv(const float* p) {
    unsigned a = (unsigned)__cvta_generic_to_shared(p);
    unsigned v;
    asm volatile(
        "{\n\t.reg .pred sp;\n"
        "SPINS%=:\n\t"
        "ld.volatile.shared.b32 %0, [%1];\n\t"
        "setp.eq.u32 sp, %0, 0x7fc00000;\n\t"
        "@sp bra SPINS%=;\n\t}"
        : "=r"(v) : "r"(a) : "memory");
    return __uint_as_float(v);
}
__device__ __forceinline__ void sts_vol(float* p, float v) {
    unsigned a = (unsigned)__cvta_generic_to_shared(p);
    asm volatile("st.volatile.shared.b32 [%0], %1;" :: "r"(a), "f"(v) : "memory");
}

// ---------------------------------------------------------------------------
// Kernel 1: pairwise sqdist * log2(e) packed into g_Dq.
// 64x64 tiles (i-tile == warp row-group W), 256 threads, 4x4 microtiles.
// ---------------------------------------------------------------------------
__global__ void __launch_bounds__(256) pairdist_kernel(
    const float* __restrict__ X, const float* __restrict__ Y)
{
    __shared__ __align__(16) float Xs[64 * 68];
    __shared__ __align__(16) float Ys[64 * 68];
    __shared__ __align__(16) float x2s[64];
    __shared__ __align__(16) float y2s[64];
    __shared__ __align__(16) float stage[64 * 66];   // stage[jl*66 + il]

    const int b  = blockIdx.z;
    const int i0 = blockIdx.x * 64;                  // W = blockIdx.x
    const int j0 = blockIdx.y * 64;
    const int tid = threadIdx.x;

    const float* Xb = X + ((size_t)b * NM + i0) * DIMK;
    const float* Yb = Y + ((size_t)b * NM + j0) * DIMK;

    for (int t = tid; t < 64 * 64; t += 256) {
        int r = t >> 6, k = t & 63;
        Xs[k * 68 + r] = Xb[r * DIMK + k];
        Ys[k * 68 + r] = Yb[r * DIMK + k];
    }
    __syncthreads();

    if (tid < 128) {
        int r = tid & 63;
        const float* S = (tid < 64) ? Xs : Ys;
        float acc = 0.f;
        #pragma unroll 8
        for (int k = 0; k < 64; ++k) { float v = S[k * 68 + r]; acc += v * v; }
        if (tid < 64) x2s[r] = acc; else y2s[r] = acc;
    }
    __syncthreads();

    const int tx = tid & 15, ty = tid >> 4;
    float acc[4][4];
    #pragma unroll
    for (int a = 0; a < 4; ++a)
        #pragma unroll
        for (int c = 0; c < 4; ++c) acc[a][c] = 0.f;

    #pragma unroll 8
    for (int k = 0; k < 64; ++k) {
        float4 xv = *(const float4*)&Xs[k * 68 + 4 * tx];
        float4 yv = *(const float4*)&Ys[k * 68 + 4 * ty];
        float xr[4] = {xv.x, xv.y, xv.z, xv.w};
        float yr[4] = {yv.x, yv.y, yv.z, yv.w};
        #pragma unroll
        for (int jj = 0; jj < 4; ++jj)
            #pragma unroll
            for (int ii = 0; ii < 4; ++ii)
                acc[jj][ii] += yr[jj] * xr[ii];
    }

    const float L2E = 1.4426950408889634f;
    float4 x2v = *(const float4*)&x2s[4 * tx];
    float xr2[4] = {x2v.x, x2v.y, x2v.z, x2v.w};
    #pragma unroll
    for (int jj = 0; jj < 4; ++jj) {
        float y2 = y2s[4 * ty + jj];
        #pragma unroll
        for (int ii = 0; ii < 4; ++ii)
            stage[(4 * ty + jj) * 66 + 4 * tx + ii] =
                (xr2[ii] + y2 - 2.f * acc[jj][ii]) * L2E;
    }
    __syncthreads();

    // Packed writeout: local step row c = jl + 2k; lane = k.
    const int wk   = tid >> 5;
    const int lane = tid & 31;
    float2* gout = (float2*)g_Dq + ((size_t)(b * 8 + blockIdx.x) * UROWS + j0) * 32;
    for (int c = wk; c < 126; c += 8) {
        int jl = c - 2 * lane;
        if ((unsigned)jl < 64u) {
            float2 p = *(const float2*)&stage[jl * 66 + 2 * lane];
            gout[(size_t)c * 32 + lane] = p;
        }
    }
}

// ---------------------------------------------------------------------------
// Kernel 2: soft-DTW, skew-2 wavefront, software-pipelined. 1 CTA/batch,
// 8 warps. Lane k of warp w owns rows 64w+2k, +1; local step u covers col
// j = u-2k. Iteration u computes v0(u) AND v1(u-1) (parallel 52-cyc chains).
// Both EX2s of each softmin fused into ONE MUFU op via ex2.approx.f16x2.
// ---------------------------------------------------------------------------
__global__ void __launch_bounds__(256, 1) sdtw_kernel(float* __restrict__ out)
{
    __shared__ __align__(16) float rings[9][RING];

    const int b    = blockIdx.x;
    const int tid  = threadIdx.x;
    const int w    = tid >> 5;
    const int lane = tid & 31;
    const bool is0  = (lane == 0);
    const bool is31 = (lane == 31);

    for (int t = tid; t < 9 * RING; t += 256) {
        int r = t / RING, s = t % RING;
        bool sent = (r >= 1) && (s < 576);
        rings[0][t] = sent ? __uint_as_float(SENTU) : BIGF;   // flat fill
    }
    __syncthreads();

    // D prefetch ring (float2 per lane per step).
    const float2* dp0 = (const float2*)g_Dq + (size_t)(b * 8 + w) * UROWS * 32 + lane;
    float2 dring[8];
    #pragma unroll
    for (int p = 0; p < 8; ++p) dring[p] = dp0[p * 32];
    const float2* dp = dp0 + 8 * 32;

    const float* rring = rings[w];       // consumer: value(col c) at slot c+63
    float*       wring = rings[w + 1];   // producer: iter u writes slot u

    // Prefill: P(-1) at slot 62, P(0) at slot 63.
    float pm1 = spinv(rring + 62);
    float p0  = spinv(rring + 63);
    if (lane != 0) { pm1 = BIGF; p0 = BIGF; }
    if (w == 0 && lane == 0) pm1 = 0.0f;      // origin: R[-1][-1] = 0
    float lo0  = fminf(pm1, p0), hi0 = fmaxf(pm1, p0);
    float pNow = p0;

    // First chunk: slots 64..71 = P(1..8).
    float bnd[8];
    {
        (void)spinv(rring + 71);
        float4 c0 = *(const float4*)(rring + 64);
        float4 c1 = *(const float4*)(rring + 68);
        bnd[0]=c0.x; bnd[1]=c0.y; bnd[2]=c0.z; bnd[3]=c0.w;
        bnd[4]=c1.x; bnd[5]=c1.y; bnd[6]=c1.z; bnd[7]=c1.w;
    }

    float v0p  = BIGF;                 // v0(u-1)
    float d2yp = 0.f;                  // d(u-1).y
    float lo1p = BIGF, hi1p = BIGF;    // min/max(v0(u-2), v1(u-2))
    float res  = 0.f;

    for (int B = 0; B < 576; B += 8) {
        #pragma unroll
        for (int x = 0; x < 8; ++x) {
            float2 d2 = dring[x];
            dring[x] = dp[x * 32];                 // prefetch step u+8

            // cell0(u): softmin(P(j-1), P(j), v0(u-1)); dual-exp in 1 MUFU
            float m0 = fminf(lo0, v0p);
            float x0 = fmaxf(lo0, v0p);
            float q0 = ex2_pair(m0 - x0, m0 - hi0);
            float v0 = (d2.x + m0) - lg2f(q0 + 1.0f);

            // cell1(u-1): softmin(v0(u-2), v1(u-2), v0(u-1)) -- parallel chain
            float m1  = fminf(lo1p, v0p);
            float x1  = fmaxf(lo1p, v0p);
            float q1  = ex2_pair(m1 - x1, m1 - hi1p);
            float v1m = (d2yp + m1) - lg2f(q1 + 1.0f);

            if (x == 6) { if (B == 568) res = v1m; }   // iter 574 -> v1(573) = R[511][511]

            if (is31) sts_vol(wring + (B + x), v1m);   // publish slot u

            float sh = __shfl_up_sync(0xffffffffu, v1m, 1);
            float newv = is0 ? bnd[x] : sh;            // P(u+1)

            if (x == 7) {                              // next chunk: slots B+72..79
                (void)spinv(rring + B + 79);
                float4 c0 = *(const float4*)(rring + B + 72);
                float4 c1 = *(const float4*)(rring + B + 76);
                bnd[0]=c0.x; bnd[1]=c0.y; bnd[2]=c0.z; bnd[3]=c0.w;
                bnd[4]=c1.x; bnd[5]=c1.y; bnd[6]=c1.z; bnd[7]=c1.w;
            }

            // rolls (off the v0 chain)
            lo1p = fminf(v0p, v1m);
            hi1p = fmaxf(v0p, v1m);
            lo0  = fminf(pNow, newv);
            hi0  = fmaxf(pNow, newv);
            pNow = newv;
            v0p  = v0;
            d2yp = d2.y;
        }
        dp += 8 * 32;
    }

    if (tid == 255)
        out[b] = res * 0.69314718055994531f;           // log2 -> natural domain
}

extern "C" void kernel_launch(void* const* d_in, const int* in_sizes, int n_in,
                              void* d_out, int out_size)
{
    (void)in_sizes; (void)n_in; (void)out_size;
    const float* X = (const float*)d_in[0];
    const float* Y = (const float*)d_in[1];
    float* out = (float*)d_out;

    dim3 g1(NM / 64, NM / 64, BATCH);
    pairdist_kernel<<<g1, 256>>>(X, Y);
    sdtw_kernel<<<BATCH, 256>>>(out);
}